// round 14
// baseline (speedup 1.0000x reference)
#include <cuda_runtime.h>
#include <cuda_fp16.h>
#include <math.h>
#include <stdint.h>

#define NMAX 50000
#define EMAX 800000
#define ETOTMAX (EMAX + NMAX)
#define GMAX 64
#define LN_EPS 1e-5f
#define SLOPE 0.2f

// ---------------- scratch (static device globals; no runtime alloc) ----------
__device__ uint4 g_h16_raw[(size_t)NMAX * 32];  // fp16 features, 16B-aligned (256 halves/node)
__device__ float g_in  [(size_t)NMAX * 256];    // normalized features (input to next layer)
__device__ float g_esrc[NMAX * 4];
__device__ float g_edst[NMAX * 4];
__device__ int   g_deg [NMAX + 1];
__device__ int   g_off [NMAX + 1];
__device__ int   g_cur [NMAX];
__device__ int   g_csr [ETOTMAX];
__device__ int   g_bsum[256];
__device__ int   g_boff[256];

// ---------------- CSR build --------------------------------------------------
__global__ void init_deg_kernel(int* __restrict__ deg, int* __restrict__ cur, int Nn) {
    int i = blockIdx.x * blockDim.x + threadIdx.x;
    if (i < Nn) { deg[i] = 1; cur[i] = 0; }   // deg starts at 1: self-loop
}

__global__ void deg_hist_kernel(const int* __restrict__ dst, int E_, int* __restrict__ deg) {
    int i = blockIdx.x * blockDim.x + threadIdx.x;
    if (i < E_) atomicAdd(&deg[dst[i]], 1);
}

// fast 3-kernel exclusive scan over n<=65536 ints (256-per-block)
__global__ void block_sum_kernel(const int* __restrict__ deg, int* __restrict__ bsum, int n) {
    __shared__ int red[256];
    int idx = blockIdx.x * 256 + threadIdx.x;
    red[threadIdx.x] = (idx < n) ? deg[idx] : 0;
    __syncthreads();
    for (int s = 128; s > 0; s >>= 1) {
        if (threadIdx.x < s) red[threadIdx.x] += red[threadIdx.x + s];
        __syncthreads();
    }
    if (threadIdx.x == 0) bsum[blockIdx.x] = red[0];
}

__global__ void scan_bsums_kernel(const int* __restrict__ bsum, int* __restrict__ boff,
                                  int nb, int* __restrict__ off, int n) {
    __shared__ int ws[8];
    int tid = threadIdx.x, lane = tid & 31, wid = tid >> 5;   // 256 threads
    int v = (tid < nb) ? bsum[tid] : 0;
    int incl = v;
#pragma unroll
    for (int d = 1; d < 32; d <<= 1) {
        int t = __shfl_up_sync(0xffffffffu, incl, d);
        if (lane >= d) incl += t;
    }
    if (lane == 31) ws[wid] = incl;
    __syncthreads();
    if (tid == 0) {
        int c = 0;
#pragma unroll
        for (int i = 0; i < 8; i++) { int t = ws[i]; ws[i] = c; c += t; }
        off[n] = c;   // total
    }
    __syncthreads();
    if (tid < nb) boff[tid] = ws[wid] + incl - v;
}

__global__ void block_scan_kernel(const int* __restrict__ deg, const int* __restrict__ boff,
                                  int* __restrict__ off, int n) {
    __shared__ int ws[8];
    int idx = blockIdx.x * 256 + threadIdx.x;
    int lane = threadIdx.x & 31, wid = threadIdx.x >> 5;
    int v = (idx < n) ? deg[idx] : 0;
    int incl = v;
#pragma unroll
    for (int d = 1; d < 32; d <<= 1) {
        int t = __shfl_up_sync(0xffffffffu, incl, d);
        if (lane >= d) incl += t;
    }
    if (lane == 31) ws[wid] = incl;
    __syncthreads();
    if (threadIdx.x == 0) {
        int c = 0;
#pragma unroll
        for (int i = 0; i < 8; i++) { int t = ws[i]; ws[i] = c; c += t; }
    }
    __syncthreads();
    if (idx < n) off[idx] = boff[blockIdx.x] + ws[wid] + incl - v;
}

__global__ void csr_scatter_kernel(const int* __restrict__ src, const int* __restrict__ dst,
                                   int E_, int Etot,
                                   const int* __restrict__ off, int* __restrict__ cur,
                                   int* __restrict__ csr_src) {
    int i = blockIdx.x * blockDim.x + threadIdx.x;
    if (i >= Etot) return;
    int s, d;
    if (i < E_) { s = src[i]; d = dst[i]; } else { s = d = i - E_; }
    int pos = off[d] + atomicAdd(&cur[d], 1);
    csr_src[pos] = s;
}

// ---------------- fp16 tensor-core GEMM helpers ------------------------------
#define MMA_F16(d, a, b0, b1)                                                \
    asm volatile("mma.sync.aligned.m16n8k16.row.col.f32.f16.f16.f32 "        \
                 "{%0,%1,%2,%3}, {%4,%5,%6,%7}, {%8,%9}, {%0,%1,%2,%3};\n"   \
                 : "+f"(d[0]), "+f"(d[1]), "+f"(d[2]), "+f"(d[3])            \
                 : "r"(a[0]), "r"(a[1]), "r"(a[2]), "r"(a[3]),               \
                   "r"(b0), "r"(b1))

__device__ __forceinline__ uint32_t pack_f16(float v0, float v1) {
    __half h0 = __float2half_rn(v0);
    __half h1 = __float2half_rn(v1);
    return (uint32_t)__half_as_ushort(h0) | ((uint32_t)__half_as_ushort(h1) << 16);
}

// ---------------- BN=256 GEMM (N fixed 256), 512 threads, 16 warps -----------
// Each A stripe read exactly once (grid.x == 1). Fused scores epilogue; head
// of a warp's 64-col slice = wx.
__global__ __launch_bounds__(512) void f16_gemm256_scores_kernel(
        const float* __restrict__ A, const float* __restrict__ B,
        __half2* __restrict__ C16,
        const float* __restrict__ asrc, const float* __restrict__ adst,
        float* __restrict__ esrc, float* __restrict__ edst,
        int M, int K) {
    const int N = 256;
    __shared__ uint32_t As[2][128 * 9];
    __shared__ uint32_t Bs[2][256 * 9];

    const int tid  = threadIdx.x;
    const int warp = tid >> 5, lane = tid & 31;
    const int g = lane >> 2, tg = lane & 3;
    const int wy = warp & 3;    // 4 warps along M (32 rows each)
    const int wx = warp >> 2;   // 4 warps along N (64 cols each)
    const int bm = blockIdx.y * 128;

    // A loader: thread -> row ar (0..127), cols ac4..ac4+3
    const int ar  = tid >> 2;
    const int ac4 = (tid & 3) * 4;
    // B loader: warp kp/half, lanes cover 4 consecutive n each
    const int kp   = warp & 7;          // k-pair rows 2kp, 2kp+1
    const int bn0  = (warp >> 3) * 128 + lane * 4;

    float acc[2][8][4];
#pragma unroll
    for (int mt = 0; mt < 2; mt++)
#pragma unroll
        for (int nt = 0; nt < 8; nt++)
#pragma unroll
            for (int c = 0; c < 4; c++) acc[mt][nt][c] = 0.f;

    const int T = K >> 4;
    const bool arow_ok = (bm + ar) < M;

    float4 av, b0v, b1v;
    av = arow_ok ? *(const float4*)(A + (size_t)(bm + ar) * K + ac4)
                 : make_float4(0.f, 0.f, 0.f, 0.f);
    b0v = *(const float4*)(B + (size_t)(2 * kp) * N + bn0);
    b1v = *(const float4*)(B + (size_t)(2 * kp + 1) * N + bn0);
    {
        const int buf = 0;
        As[buf][ar * 9 + (ac4 >> 1)]     = pack_f16(av.x, av.y);
        As[buf][ar * 9 + (ac4 >> 1) + 1] = pack_f16(av.z, av.w);
        const float* b0p = &b0v.x;
        const float* b1p = &b1v.x;
#pragma unroll
        for (int j = 0; j < 4; j++)
            Bs[buf][(bn0 + j) * 9 + kp] = pack_f16(b0p[j], b1p[j]);
    }
    __syncthreads();

    for (int t = 0; t < T; t++) {
        const int buf = t & 1;
        if (t + 1 < T) {
            int k0 = (t + 1) << 4;
            if (arow_ok)
                av = *(const float4*)(A + (size_t)(bm + ar) * K + k0 + ac4);
            b0v = *(const float4*)(B + (size_t)(k0 + 2 * kp) * N + bn0);
            b1v = *(const float4*)(B + (size_t)(k0 + 2 * kp + 1) * N + bn0);
        }

        uint32_t ah[2][4];
#pragma unroll
        for (int mt = 0; mt < 2; mt++) {
            int r0 = (wy * 32 + mt * 16 + g) * 9 + tg;
            int r1 = r0 + 8 * 9;
            ah[mt][0] = As[buf][r0];
            ah[mt][1] = As[buf][r1];
            ah[mt][2] = As[buf][r0 + 4];
            ah[mt][3] = As[buf][r1 + 4];
        }
#pragma unroll
        for (int nt = 0; nt < 8; nt++) {
            int ni = (wx * 64 + nt * 8 + g) * 9 + tg;
            uint32_t bh0 = Bs[buf][ni];
            uint32_t bh1 = Bs[buf][ni + 4];
#pragma unroll
            for (int mt = 0; mt < 2; mt++)
                MMA_F16(acc[mt][nt], ah[mt], bh0, bh1);
        }

        if (t + 1 < T) {
            const int nbuf = (t + 1) & 1;
            As[nbuf][ar * 9 + (ac4 >> 1)]     = pack_f16(av.x, av.y);
            As[nbuf][ar * 9 + (ac4 >> 1) + 1] = pack_f16(av.z, av.w);
            const float* b0p = &b0v.x;
            const float* b1p = &b1v.x;
#pragma unroll
            for (int j = 0; j < 4; j++)
                Bs[nbuf][(bn0 + j) * 9 + kp] = pack_f16(b0p[j], b1p[j]);
        }
        __syncthreads();
    }

    // ---- epilogue 1: write C as fp16 ----
#pragma unroll
    for (int mt = 0; mt < 2; mt++) {
        int gr0 = bm + wy * 32 + mt * 16 + g;
        int gr1 = gr0 + 8;
#pragma unroll
        for (int nt = 0; nt < 8; nt++) {
            int col = wx * 64 + nt * 8 + 2 * tg;
            if (gr0 < M)
                C16[((size_t)gr0 * N + col) >> 1] =
                    __floats2half2_rn(acc[mt][nt][0], acc[mt][nt][1]);
            if (gr1 < M)
                C16[((size_t)gr1 * N + col) >> 1] =
                    __floats2half2_rn(acc[mt][nt][2], acc[mt][nt][3]);
        }
    }

    // ---- epilogue 2: fused attention scores (head = wx) ----
    float psrc[2][2] = {};
    float pdst[2][2] = {};
#pragma unroll
    for (int nt = 0; nt < 8; nt++) {
        int gc = wx * 64 + nt * 8 + 2 * tg;
        float2 as = *(const float2*)&asrc[gc];
        float2 ad = *(const float2*)&adst[gc];
#pragma unroll
        for (int mt = 0; mt < 2; mt++) {
            psrc[mt][0] += acc[mt][nt][0] * as.x + acc[mt][nt][1] * as.y;
            psrc[mt][1] += acc[mt][nt][2] * as.x + acc[mt][nt][3] * as.y;
            pdst[mt][0] += acc[mt][nt][0] * ad.x + acc[mt][nt][1] * ad.y;
            pdst[mt][1] += acc[mt][nt][2] * ad.x + acc[mt][nt][3] * ad.y;
        }
    }
#pragma unroll
    for (int mt = 0; mt < 2; mt++)
#pragma unroll
        for (int rh = 0; rh < 2; rh++) {
            float s1 = psrc[mt][rh], s2 = pdst[mt][rh];
            s1 += __shfl_xor_sync(0xffffffffu, s1, 1);
            s1 += __shfl_xor_sync(0xffffffffu, s1, 2);
            s2 += __shfl_xor_sync(0xffffffffu, s2, 1);
            s2 += __shfl_xor_sync(0xffffffffu, s2, 2);
            psrc[mt][rh] = s1;
            pdst[mt][rh] = s2;
        }
    if (tg == 0) {
#pragma unroll
        for (int mt = 0; mt < 2; mt++)
#pragma unroll
            for (int rh = 0; rh < 2; rh++) {
                int gr = bm + wy * 32 + mt * 16 + g + rh * 8;
                if (gr < M) {
                    esrc[gr * 4 + wx] = psrc[mt][rh];
                    edst[gr * 4 + wx] = pdst[mt][rh];
                }
            }
    }
}

// ---------------- BN=128 GEMM (for HC=128 layer), 256 threads ----------------
template<int LOGC>
__global__ __launch_bounds__(256) void f16_gemm_scores_kernel(
        const float* __restrict__ A, const float* __restrict__ B,
        __half2* __restrict__ C16,
        const float* __restrict__ asrc, const float* __restrict__ adst,
        float* __restrict__ esrc, float* __restrict__ edst,
        int M, int K, int N) {
    __shared__ uint32_t As[2][128 * 9];
    __shared__ uint32_t Bs[2][128 * 9];

    const int tid  = threadIdx.x;
    const int warp = tid >> 5, lane = tid & 31;
    const int g = lane >> 2, tg = lane & 3;
    const int wy = warp & 3;
    const int wx = warp >> 2;
    const int bm = blockIdx.y * 128, bn = blockIdx.x * 128;

    const int ar = tid >> 1;
    const int ac = (tid & 1) * 8;
    const int kp = warp;
    const int n0 = lane * 4;

    float acc[2][8][4];
#pragma unroll
    for (int mt = 0; mt < 2; mt++)
#pragma unroll
        for (int nt = 0; nt < 8; nt++)
#pragma unroll
            for (int c = 0; c < 4; c++) acc[mt][nt][c] = 0.f;

    const int T = K >> 4;
    const bool arow_ok = (bm + ar) < M;

    float4 a0v, a1v, b0v, b1v;
    if (arow_ok) {
        a0v = *(const float4*)(A + (size_t)(bm + ar) * K + ac);
        a1v = *(const float4*)(A + (size_t)(bm + ar) * K + ac + 4);
    } else {
        a0v = a1v = make_float4(0.f, 0.f, 0.f, 0.f);
    }
    b0v = *(const float4*)(B + (size_t)(2 * kp) * N + bn + n0);
    b1v = *(const float4*)(B + (size_t)(2 * kp + 1) * N + bn + n0);
    {
        const int buf = 0;
        const float* a0p = &a0v.x;
        const float* a1p = &a1v.x;
#pragma unroll
        for (int j = 0; j < 2; j++) {
            As[buf][ar * 9 + (ac >> 1) + j]     = pack_f16(a0p[2 * j], a0p[2 * j + 1]);
            As[buf][ar * 9 + (ac >> 1) + 2 + j] = pack_f16(a1p[2 * j], a1p[2 * j + 1]);
        }
        const float* b0p = &b0v.x;
        const float* b1p = &b1v.x;
#pragma unroll
        for (int j = 0; j < 4; j++)
            Bs[buf][(n0 + j) * 9 + kp] = pack_f16(b0p[j], b1p[j]);
    }
    __syncthreads();

    for (int t = 0; t < T; t++) {
        const int buf = t & 1;
        if (t + 1 < T) {
            int k0 = (t + 1) << 4;
            if (arow_ok) {
                a0v = *(const float4*)(A + (size_t)(bm + ar) * K + k0 + ac);
                a1v = *(const float4*)(A + (size_t)(bm + ar) * K + k0 + ac + 4);
            }
            b0v = *(const float4*)(B + (size_t)(k0 + 2 * kp) * N + bn + n0);
            b1v = *(const float4*)(B + (size_t)(k0 + 2 * kp + 1) * N + bn + n0);
        }

        uint32_t ah[2][4];
#pragma unroll
        for (int mt = 0; mt < 2; mt++) {
            int r0 = (wy * 32 + mt * 16 + g) * 9 + tg;
            int r1 = r0 + 8 * 9;
            ah[mt][0] = As[buf][r0];
            ah[mt][1] = As[buf][r1];
            ah[mt][2] = As[buf][r0 + 4];
            ah[mt][3] = As[buf][r1 + 4];
        }
#pragma unroll
        for (int nt = 0; nt < 8; nt++) {
            int ni = (wx * 64 + nt * 8 + g) * 9 + tg;
            uint32_t bh0 = Bs[buf][ni];
            uint32_t bh1 = Bs[buf][ni + 4];
#pragma unroll
            for (int mt = 0; mt < 2; mt++)
                MMA_F16(acc[mt][nt], ah[mt], bh0, bh1);
        }

        if (t + 1 < T) {
            const int nbuf = (t + 1) & 1;
            const float* a0p = &a0v.x;
            const float* a1p = &a1v.x;
#pragma unroll
            for (int j = 0; j < 2; j++) {
                As[nbuf][ar * 9 + (ac >> 1) + j]     = pack_f16(a0p[2 * j], a0p[2 * j + 1]);
                As[nbuf][ar * 9 + (ac >> 1) + 2 + j] = pack_f16(a1p[2 * j], a1p[2 * j + 1]);
            }
            const float* b0p = &b0v.x;
            const float* b1p = &b1v.x;
#pragma unroll
            for (int j = 0; j < 4; j++)
                Bs[nbuf][(n0 + j) * 9 + kp] = pack_f16(b0p[j], b1p[j]);
        }
        __syncthreads();
    }

#pragma unroll
    for (int mt = 0; mt < 2; mt++) {
        int gr0 = bm + wy * 32 + mt * 16 + g;
        int gr1 = gr0 + 8;
#pragma unroll
        for (int nt = 0; nt < 8; nt++) {
            int col = bn + wx * 64 + nt * 8 + 2 * tg;
            if (gr0 < M)
                C16[((size_t)gr0 * N + col) >> 1] =
                    __floats2half2_rn(acc[mt][nt][0], acc[mt][nt][1]);
            if (gr1 < M)
                C16[((size_t)gr1 * N + col) >> 1] =
                    __floats2half2_rn(acc[mt][nt][2], acc[mt][nt][3]);
        }
    }

    const int NSLOT = (LOGC == 6) ? 1 : 2;
    float psrc[2][2][2] = {};
    float pdst[2][2][2] = {};
#pragma unroll
    for (int nt = 0; nt < 8; nt++) {
        int gc = bn + wx * 64 + nt * 8 + 2 * tg;
        float2 as = *(const float2*)&asrc[gc];
        float2 ad = *(const float2*)&adst[gc];
        int hs = (LOGC == 6) ? 0 : (nt >> 2);
#pragma unroll
        for (int mt = 0; mt < 2; mt++) {
            psrc[mt][0][hs] += acc[mt][nt][0] * as.x + acc[mt][nt][1] * as.y;
            psrc[mt][1][hs] += acc[mt][nt][2] * as.x + acc[mt][nt][3] * as.y;
            pdst[mt][0][hs] += acc[mt][nt][0] * ad.x + acc[mt][nt][1] * ad.y;
            pdst[mt][1][hs] += acc[mt][nt][2] * ad.x + acc[mt][nt][3] * ad.y;
        }
    }
#pragma unroll
    for (int mt = 0; mt < 2; mt++)
#pragma unroll
        for (int rh = 0; rh < 2; rh++)
#pragma unroll
            for (int hs = 0; hs < NSLOT; hs++) {
                float s1 = psrc[mt][rh][hs], s2 = pdst[mt][rh][hs];
                s1 += __shfl_xor_sync(0xffffffffu, s1, 1);
                s1 += __shfl_xor_sync(0xffffffffu, s1, 2);
                s2 += __shfl_xor_sync(0xffffffffu, s2, 1);
                s2 += __shfl_xor_sync(0xffffffffu, s2, 2);
                psrc[mt][rh][hs] = s1;
                pdst[mt][rh][hs] = s2;
            }
    if (tg == 0) {
#pragma unroll
        for (int mt = 0; mt < 2; mt++)
#pragma unroll
            for (int rh = 0; rh < 2; rh++) {
                int gr = bm + wy * 32 + mt * 16 + g + rh * 8;
                if (gr < M) {
#pragma unroll
                    for (int hs = 0; hs < NSLOT; hs++) {
                        int hd = (LOGC == 6) ? ((bn >> 6) + wx) : (wx * 2 + hs);
                        esrc[gr * 4 + hd] = psrc[mt][rh][hs];
                        edst[gr * 4 + hd] = pdst[mt][rh][hs];
                    }
                }
            }
    }
}

// ---------------- fused aggregation: two-pass, warp per dst node -------------
template<int HPL, int DOELU>
__global__ __launch_bounds__(256) void gat_agg_kernel(
        const __half2* __restrict__ h16,
        const float* __restrict__ esrc, const float* __restrict__ edst,
        const int* __restrict__ off, const int* __restrict__ csr_src,
        const float* __restrict__ bias,
        const float* __restrict__ gam, const float* __restrict__ bet,
        float* __restrict__ outp, int Nn) {
    const int HC  = HPL * 32;
    const int HC2 = HPL * 16;      // half2 words per node
    __shared__ float sp[8][32][4];
    __shared__ int   si[8][32];

    int wslot = threadIdx.x >> 5;
    int n = (blockIdx.x * blockDim.x + threadIdx.x) >> 5;
    int lane = threadIdx.x & 31;
    if (n >= Nn) return;
    int hd = lane >> 3;

    int beg = off[n], end = off[n + 1];
    float4 ed = ((const float4*)edst)[n];

    // pass 1: segment max per head
    float m0 = -INFINITY, m1 = -INFINITY, m2 = -INFINITY, m3 = -INFINITY;
    for (int i = beg + lane; i < end; i += 32) {
        int s = csr_src[i];
        float4 es = ((const float4*)esrc)[s];
        float e0 = es.x + ed.x; e0 = e0 > 0.f ? e0 : SLOPE * e0; m0 = fmaxf(m0, e0);
        float e1 = es.y + ed.y; e1 = e1 > 0.f ? e1 : SLOPE * e1; m1 = fmaxf(m1, e1);
        float e2 = es.z + ed.z; e2 = e2 > 0.f ? e2 : SLOPE * e2; m2 = fmaxf(m2, e2);
        float e3 = es.w + ed.w; e3 = e3 > 0.f ? e3 : SLOPE * e3; m3 = fmaxf(m3, e3);
    }
#pragma unroll
    for (int d = 16; d > 0; d >>= 1) {
        m0 = fmaxf(m0, __shfl_xor_sync(0xffffffffu, m0, d));
        m1 = fmaxf(m1, __shfl_xor_sync(0xffffffffu, m1, d));
        m2 = fmaxf(m2, __shfl_xor_sync(0xffffffffu, m2, d));
        m3 = fmaxf(m3, __shfl_xor_sync(0xffffffffu, m3, d));
    }

    // pass 2
    float acc[HPL];
#pragma unroll
    for (int j = 0; j < HPL; j++) acc[j] = 0.f;
    float den = 0.f;

    for (int i = beg; i < end; i += 32) {
        int cnt = min(32, end - i);
        int s_l = 0;
        float p0 = 0.f, p1 = 0.f, p2 = 0.f, p3 = 0.f;
        if (lane < cnt) {
            s_l = csr_src[i + lane];
            float4 es = ((const float4*)esrc)[s_l];
            float e0 = es.x + ed.x; e0 = e0 > 0.f ? e0 : SLOPE * e0;
            float e1 = es.y + ed.y; e1 = e1 > 0.f ? e1 : SLOPE * e1;
            float e2 = es.z + ed.z; e2 = e2 > 0.f ? e2 : SLOPE * e2;
            float e3 = es.w + ed.w; e3 = e3 > 0.f ? e3 : SLOPE * e3;
            p0 = __expf(e0 - m0); p1 = __expf(e1 - m1);
            p2 = __expf(e2 - m2); p3 = __expf(e3 - m3);
        }
        si[wslot][lane] = s_l;
        *(float4*)&sp[wslot][lane][0] = make_float4(p0, p1, p2, p3);
        __syncwarp();

        int k = 0;
        for (; k + 8 <= cnt; k += 8) {
            uint4 v8[8];
            uint2 v4[8];
#pragma unroll
            for (int u = 0; u < 8; u++) {
                int ss = si[wslot][k + u];
                const uint32_t* rp = (const uint32_t*)(h16 + (size_t)ss * HC2);
                if (HPL == 8) v8[u] = ((const uint4*)rp)[lane];
                else          v4[u] = ((const uint2*)rp)[lane];
            }
#pragma unroll
            for (int u = 0; u < 8; u++) {
                float q = sp[wslot][k + u][hd];
                den += q;
                uint32_t w[4];
                if (HPL == 8) { w[0] = v8[u].x; w[1] = v8[u].y; w[2] = v8[u].z; w[3] = v8[u].w; }
                else          { w[0] = v4[u].x; w[1] = v4[u].y; w[2] = 0; w[3] = 0; }
#pragma unroll
                for (int j = 0; j < HPL / 2; j++) {
                    float2 f = __half22float2(*(const __half2*)&w[j]);
                    acc[2 * j]     += q * f.x;
                    acc[2 * j + 1] += q * f.y;
                }
            }
        }
        for (; k < cnt; k++) {
            int   ss = si[wslot][k];
            float q  = sp[wslot][k][hd];
            den += q;
            const uint32_t* rp = (const uint32_t*)(h16 + (size_t)ss * HC2);
            uint32_t w[4];
            if (HPL == 8) {
                uint4 v = ((const uint4*)rp)[lane];
                w[0] = v.x; w[1] = v.y; w[2] = v.z; w[3] = v.w;
            } else {
                uint2 v = ((const uint2*)rp)[lane];
                w[0] = v.x; w[1] = v.y; w[2] = 0; w[3] = 0;
            }
#pragma unroll
            for (int j = 0; j < HPL / 2; j++) {
                float2 f = __half22float2(*(const __half2*)&w[j]);
                acc[2 * j]     += q * f.x;
                acc[2 * j + 1] += q * f.y;
            }
        }
        __syncwarp();
    }

    // epilogue: /den, +bias, (ELU), LayerNorm — all coalesced float4
    int fb = lane * HPL;
    float vals[HPL];
    float sum = 0.f;
#pragma unroll
    for (int j = 0; j < HPL; j += 4) {
        float4 b = *(const float4*)&bias[fb + j];
        float v0 = acc[j]     / den + b.x;
        float v1 = acc[j + 1] / den + b.y;
        float v2 = acc[j + 2] / den + b.z;
        float v3 = acc[j + 3] / den + b.w;
        if (DOELU) {
            v0 = v0 > 0.f ? v0 : expm1f(v0);
            v1 = v1 > 0.f ? v1 : expm1f(v1);
            v2 = v2 > 0.f ? v2 : expm1f(v2);
            v3 = v3 > 0.f ? v3 : expm1f(v3);
        }
        vals[j] = v0; vals[j + 1] = v1; vals[j + 2] = v2; vals[j + 3] = v3;
        sum += v0 + v1 + v2 + v3;
    }
#pragma unroll
    for (int d = 16; d > 0; d >>= 1) sum += __shfl_xor_sync(0xffffffffu, sum, d);
    float mu = sum / (float)HC;
    float vs = 0.f;
#pragma unroll
    for (int j = 0; j < HPL; j++) {
        float dv = vals[j] - mu;
        vs += dv * dv;
    }
#pragma unroll
    for (int d = 16; d > 0; d >>= 1) vs += __shfl_xor_sync(0xffffffffu, vs, d);
    float rstd = rsqrtf(vs / (float)HC + LN_EPS);
#pragma unroll
    for (int j = 0; j < HPL; j += 4) {
        float4 gm = *(const float4*)&gam[fb + j];
        float4 bt = *(const float4*)&bet[fb + j];
        float4 o;
        o.x = gm.x * (vals[j]     - mu) * rstd + bt.x;
        o.y = gm.y * (vals[j + 1] - mu) * rstd + bt.y;
        o.z = gm.z * (vals[j + 2] - mu) * rstd + bt.z;
        o.w = gm.w * (vals[j + 3] - mu) * rstd + bt.w;
        *(float4*)&outp[(size_t)n * HC + fb + j] = o;
    }
}

// ---------------- mean pool: block per graph, binary search (batch sorted) ---
__global__ void pool_kernel(const float* __restrict__ node_out, const int* __restrict__ batch,
                            float* __restrict__ graph_out, int Nn) {
    int g = blockIdx.x;
    int f = threadIdx.x;  // 128
    int lo = 0, hi = Nn;
    while (lo < hi) { int mid = (lo + hi) >> 1; if (batch[mid] < g) lo = mid + 1; else hi = mid; }
    int start = lo;
    lo = start; hi = Nn;
    while (lo < hi) { int mid = (lo + hi) >> 1; if (batch[mid] < g + 1) lo = mid + 1; else hi = mid; }
    int end = lo;
    float s = 0.f;
    for (int n = start; n < end; n++) s += node_out[(size_t)n * 128 + f];
    graph_out[g * 128 + f] = s / fmaxf((float)(end - start), 1.f);
}

// ---------------- launch -----------------------------------------------------
extern "C" void kernel_launch(void* const* d_in, const int* in_sizes, int n_in,
                              void* d_out, int out_size) {
    const float* x     = (const float*)d_in[0];
    const int*   ei    = (const int*)d_in[1];
    const int*   batch = (const int*)d_in[2];
    const float* W[3]    = {(const float*)d_in[3],  (const float*)d_in[9],  (const float*)d_in[15]};
    const float* asrc[3] = {(const float*)d_in[4],  (const float*)d_in[10], (const float*)d_in[16]};
    const float* adst[3] = {(const float*)d_in[5],  (const float*)d_in[11], (const float*)d_in[17]};
    const float* bia[3]  = {(const float*)d_in[6],  (const float*)d_in[12], (const float*)d_in[18]};
    const float* gam[3]  = {(const float*)d_in[7],  (const float*)d_in[13], (const float*)d_in[19]};
    const float* bet[3]  = {(const float*)d_in[8],  (const float*)d_in[14], (const float*)d_in[20]};

    int N = in_sizes[0] / 768;
    int E = in_sizes[1] / 2;
    int Etot = E + N;
    const int* srcA = ei;
    const int* dstA = ei + E;

    float* node_out  = (float*)d_out;
    float* graph_out = node_out + (size_t)N * 128;

    __half2* p_h16;
    float *p_in, *p_esrc, *p_edst;
    int *p_deg, *p_off, *p_cur, *p_csr, *p_bsum, *p_boff;
    cudaGetSymbolAddress((void**)&p_h16, g_h16_raw);
    cudaGetSymbolAddress((void**)&p_in, g_in);
    cudaGetSymbolAddress((void**)&p_esrc, g_esrc);
    cudaGetSymbolAddress((void**)&p_edst, g_edst);
    cudaGetSymbolAddress((void**)&p_deg, g_deg);
    cudaGetSymbolAddress((void**)&p_off, g_off);
    cudaGetSymbolAddress((void**)&p_cur, g_cur);
    cudaGetSymbolAddress((void**)&p_csr, g_csr);
    cudaGetSymbolAddress((void**)&p_bsum, g_bsum);
    cudaGetSymbolAddress((void**)&p_boff, g_boff);

    int dins[3] = {768, 256, 256};
    int HCs[3]  = {256, 256, 128};
    const float* inputs[3] = {x, p_in, p_in};
    float* outs[3] = {p_in, p_in, node_out};

    // launch order: GEMM L1 is the 4th launch (profiled by ncu capture)
    int nb = (N + 255) / 256;
    init_deg_kernel<<<(N + 255) / 256, 256>>>(p_deg, p_cur, N);
    deg_hist_kernel<<<(E + 255) / 256, 256>>>(dstA, E, p_deg);
    block_sum_kernel<<<nb, 256>>>(p_deg, p_bsum, N);

    // launch #4: layer-1 GEMM (BN=256, independent of CSR chain)
    {
        dim3 ggrid(1, (N + 127) / 128);
        f16_gemm256_scores_kernel<<<ggrid, 512>>>(inputs[0], W[0], p_h16,
                                                  asrc[0], adst[0], p_esrc, p_edst,
                                                  N, dins[0]);
    }

    scan_bsums_kernel<<<1, 256>>>(p_bsum, p_boff, nb, p_off, N);
    block_scan_kernel<<<nb, 256>>>(p_deg, p_boff, p_off, N);
    csr_scatter_kernel<<<(Etot + 255) / 256, 256>>>(srcA, dstA, E, Etot, p_off, p_cur, p_csr);

    int nwb = (N + 7) / 8;
    for (int L = 0; L < 3; L++) {
        int K = dins[L], HC = HCs[L];

        if (L > 0) {
            if (HC == 256) {
                dim3 ggrid(1, (N + 127) / 128);
                f16_gemm256_scores_kernel<<<ggrid, 512>>>(inputs[L], W[L], p_h16,
                                                          asrc[L], adst[L], p_esrc, p_edst,
                                                          N, K);
            } else {
                dim3 ggrid(1, (N + 127) / 128);
                f16_gemm_scores_kernel<5><<<ggrid, 256>>>(inputs[L], W[L], p_h16,
                                                          asrc[L], adst[L], p_esrc, p_edst,
                                                          N, K, HC);
            }
        }

        if (HC == 256) {
            if (L < 2)
                gat_agg_kernel<8, 1><<<nwb, 256>>>(p_h16, p_esrc, p_edst, p_off, p_csr,
                                                   bia[L], gam[L], bet[L], outs[L], N);
            else
                gat_agg_kernel<8, 0><<<nwb, 256>>>(p_h16, p_esrc, p_edst, p_off, p_csr,
                                                   bia[L], gam[L], bet[L], outs[L], N);
        } else {
            gat_agg_kernel<4, 0><<<nwb, 256>>>(p_h16, p_esrc, p_edst, p_off, p_csr,
                                               bia[L], gam[L], bet[L], outs[L], N);
        }
    }

    pool_kernel<<<GMAX, 128>>>(node_out, batch, graph_out, N);
}

// round 15
// speedup vs baseline: 1.1644x; 1.1644x over previous
#include <cuda_runtime.h>
#include <cuda_fp16.h>
#include <math.h>
#include <stdint.h>

#define NMAX 50000
#define EMAX 800000
#define ETOTMAX (EMAX + NMAX)
#define GMAX 64
#define LN_EPS 1e-5f
#define SLOPE 0.2f

// ---------------- scratch (static device globals; no runtime alloc) ----------
__device__ uint4  g_h16_raw[(size_t)NMAX * 32];   // fp16 GEMM output (256 halves/node)
__device__ uint4  g_in16_raw[(size_t)NMAX * 32];  // fp16 normalized features (next-layer input)
__device__ uint4  g_x16_raw[(size_t)NMAX * 96];   // fp16 copy of x (768 halves/node)
__device__ __half g_w16t[256 * 768 + 256 * 256 + 128 * 256];  // transposed fp16 weights
__device__ float g_esrc[NMAX * 4];
__device__ float g_edst[NMAX * 4];
__device__ int   g_deg [NMAX + 1];
__device__ int   g_off [NMAX + 1];
__device__ int   g_cur [NMAX];
__device__ int   g_csr [ETOTMAX];
__device__ int   g_bsum[256];
__device__ int   g_boff[256];

// ---------------- cp.async helpers -------------------------------------------
__device__ __forceinline__ void cp_async16(uint32_t smem_addr, const void* gptr) {
    asm volatile("cp.async.cg.shared.global [%0], [%1], 16;\n"
                 :: "r"(smem_addr), "l"(gptr));
}
#define CP_COMMIT() asm volatile("cp.async.commit_group;\n" ::: "memory")
#define CP_WAIT(N)  asm volatile("cp.async.wait_group %0;\n" :: "n"(N) : "memory")

// ---------------- input conversion -------------------------------------------
__global__ void conv_x16_kernel(const float* __restrict__ x, __half* __restrict__ x16, int n4) {
    int i = blockIdx.x * blockDim.x + threadIdx.x;
    if (i >= n4) return;
    float4 v = ((const float4*)x)[i];
    union { __half2 h2[2]; uint2 u; } pk;
    pk.h2[0] = __floats2half2_rn(v.x, v.y);
    pk.h2[1] = __floats2half2_rn(v.z, v.w);
    ((uint2*)x16)[i] = pk.u;
}

// W [K, HC] fp32 -> Wt [HC, K] fp16, 32x32 smem tiles; z selects layer
__global__ void conv_wt_kernel(const float* __restrict__ W1, const float* __restrict__ W2,
                               const float* __restrict__ W3,
                               __half* __restrict__ Wt1, __half* __restrict__ Wt2,
                               __half* __restrict__ Wt3) {
    __shared__ float tile[32][33];
    int l = blockIdx.z;
    const float* W = (l == 0) ? W1 : (l == 1) ? W2 : W3;
    __half* Wt = (l == 0) ? Wt1 : (l == 1) ? Wt2 : Wt3;
    int K  = (l == 0) ? 768 : 256;
    int HC = (l == 2) ? 128 : 256;
    int kb = blockIdx.y * 32, nb = blockIdx.x * 32;
    if (kb >= K || nb >= HC) return;
    int tx = threadIdx.x, ty = threadIdx.y;   // 32 x 8
#pragma unroll
    for (int j = 0; j < 32; j += 8)
        tile[ty + j][tx] = W[(size_t)(kb + ty + j) * HC + nb + tx];
    __syncthreads();
#pragma unroll
    for (int j = 0; j < 32; j += 8)
        Wt[(size_t)(nb + ty + j) * K + kb + tx] = __float2half_rn(tile[tx][ty + j]);
}

// ---------------- CSR build --------------------------------------------------
__global__ void init_deg_kernel(int* __restrict__ deg, int* __restrict__ cur, int Nn) {
    int i = blockIdx.x * blockDim.x + threadIdx.x;
    if (i < Nn) { deg[i] = 1; cur[i] = 0; }
}

__global__ void deg_hist_kernel(const int* __restrict__ dst, int E_, int* __restrict__ deg) {
    int i = blockIdx.x * blockDim.x + threadIdx.x;
    if (i < E_) atomicAdd(&deg[dst[i]], 1);
}

__global__ void block_sum_kernel(const int* __restrict__ deg, int* __restrict__ bsum, int n) {
    __shared__ int red[256];
    int idx = blockIdx.x * 256 + threadIdx.x;
    red[threadIdx.x] = (idx < n) ? deg[idx] : 0;
    __syncthreads();
    for (int s = 128; s > 0; s >>= 1) {
        if (threadIdx.x < s) red[threadIdx.x] += red[threadIdx.x + s];
        __syncthreads();
    }
    if (threadIdx.x == 0) bsum[blockIdx.x] = red[0];
}

__global__ void scan_bsums_kernel(const int* __restrict__ bsum, int* __restrict__ boff,
                                  int nb, int* __restrict__ off, int n) {
    __shared__ int ws[8];
    int tid = threadIdx.x, lane = tid & 31, wid = tid >> 5;
    int v = (tid < nb) ? bsum[tid] : 0;
    int incl = v;
#pragma unroll
    for (int d = 1; d < 32; d <<= 1) {
        int t = __shfl_up_sync(0xffffffffu, incl, d);
        if (lane >= d) incl += t;
    }
    if (lane == 31) ws[wid] = incl;
    __syncthreads();
    if (tid == 0) {
        int c = 0;
#pragma unroll
        for (int i = 0; i < 8; i++) { int t = ws[i]; ws[i] = c; c += t; }
        off[n] = c;
    }
    __syncthreads();
    if (tid < nb) boff[tid] = ws[wid] + incl - v;
}

__global__ void block_scan_kernel(const int* __restrict__ deg, const int* __restrict__ boff,
                                  int* __restrict__ off, int n) {
    __shared__ int ws[8];
    int idx = blockIdx.x * 256 + threadIdx.x;
    int lane = threadIdx.x & 31, wid = threadIdx.x >> 5;
    int v = (idx < n) ? deg[idx] : 0;
    int incl = v;
#pragma unroll
    for (int d = 1; d < 32; d <<= 1) {
        int t = __shfl_up_sync(0xffffffffu, incl, d);
        if (lane >= d) incl += t;
    }
    if (lane == 31) ws[wid] = incl;
    __syncthreads();
    if (threadIdx.x == 0) {
        int c = 0;
#pragma unroll
        for (int i = 0; i < 8; i++) { int t = ws[i]; ws[i] = c; c += t; }
    }
    __syncthreads();
    if (idx < n) off[idx] = boff[blockIdx.x] + ws[wid] + incl - v;
}

__global__ void csr_scatter_kernel(const int* __restrict__ src, const int* __restrict__ dst,
                                   int E_, int Etot,
                                   const int* __restrict__ off, int* __restrict__ cur,
                                   int* __restrict__ csr_src) {
    int i = blockIdx.x * blockDim.x + threadIdx.x;
    if (i >= Etot) return;
    int s, d;
    if (i < E_) { s = src[i]; d = dst[i]; } else { s = d = i - E_; }
    int pos = off[d] + atomicAdd(&cur[d], 1);
    csr_src[pos] = s;
}

// ---------------- fp16 HGEMM with cp.async, fused scores ---------------------
// C16[M,N] = A16[M,K] @ B16t[N,K]^T (both fp16, K-contiguous).
// BN=128, BK=16, 256 threads, 8 warps @ 32x64 tiles, double-buffered cp.async.
// smem rows: 16 halves (8 words) data + 4 words pad -> stride 12 words (48B),
// 16B-aligned chunks, conflict-free fragment LDS.

#define MMA_F16(d, a, b0, b1)                                                \
    asm volatile("mma.sync.aligned.m16n8k16.row.col.f32.f16.f16.f32 "        \
                 "{%0,%1,%2,%3}, {%4,%5,%6,%7}, {%8,%9}, {%0,%1,%2,%3};\n"   \
                 : "+f"(d[0]), "+f"(d[1]), "+f"(d[2]), "+f"(d[3])            \
                 : "r"(a[0]), "r"(a[1]), "r"(a[2]), "r"(a[3]),               \
                   "r"(b0), "r"(b1))

template<int LOGC>
__global__ __launch_bounds__(256) void hgemm_scores_kernel(
        const __half* __restrict__ A16, const __half* __restrict__ B16t,
        __half2* __restrict__ C16,
        const float* __restrict__ asrc, const float* __restrict__ adst,
        float* __restrict__ esrc, float* __restrict__ edst,
        int M, int K, int N) {
    __shared__ uint32_t As[2][128 * 12];
    __shared__ uint32_t Bs[2][128 * 12];

    const int tid = threadIdx.x;
    const int warp = tid >> 5, lane = tid & 31;
    const int g = lane >> 2, tg = lane & 3;
    const int wy = warp & 3, wx = warp >> 2;
    const int bm = blockIdx.y * 128, bn = blockIdx.x * 128;

    // loader: thread owns one 16B A chunk + one 16B B chunk per k-tile
    const int lrow  = tid >> 1;
    const int lpart = tid & 1;
    const bool arow_ok = (bm + lrow) < M;
    uint32_t a_dst[2], b_dst[2];
    a_dst[0] = (uint32_t)__cvta_generic_to_shared(&As[0][lrow * 12 + lpart * 4]);
    a_dst[1] = (uint32_t)__cvta_generic_to_shared(&As[1][lrow * 12 + lpart * 4]);
    b_dst[0] = (uint32_t)__cvta_generic_to_shared(&Bs[0][lrow * 12 + lpart * 4]);
    b_dst[1] = (uint32_t)__cvta_generic_to_shared(&Bs[1][lrow * 12 + lpart * 4]);
    const __half* a_src = A16 + (size_t)(bm + lrow) * K + lpart * 8;
    const __half* b_src = B16t + (size_t)(bn + lrow) * K + lpart * 8;

    // zero OOB A rows (both buffers), never overwritten
    if (!arow_ok) {
        uint4 z = make_uint4(0, 0, 0, 0);
        *(uint4*)&As[0][lrow * 12 + lpart * 4] = z;
        *(uint4*)&As[1][lrow * 12 + lpart * 4] = z;
    }

    float acc[2][8][4];
#pragma unroll
    for (int mt = 0; mt < 2; mt++)
#pragma unroll
        for (int nt = 0; nt < 8; nt++)
#pragma unroll
            for (int c = 0; c < 4; c++) acc[mt][nt][c] = 0.f;

    const int T = K >> 4;

    // prologue: tiles 0 and 1
    if (arow_ok) cp_async16(a_dst[0], a_src);
    cp_async16(b_dst[0], b_src);
    CP_COMMIT();
    if (T > 1) {
        if (arow_ok) cp_async16(a_dst[1], a_src + 16);
        cp_async16(b_dst[1], b_src + 16);
        CP_COMMIT();
    }

    for (int t = 0; t < T; t++) {
        if (t + 1 < T) { CP_WAIT(1); } else { CP_WAIT(0); }
        __syncthreads();
        const int buf = t & 1;

        uint32_t ah[2][4];
#pragma unroll
        for (int mt = 0; mt < 2; mt++) {
            int r0 = (wy * 32 + mt * 16 + g) * 12 + tg;
            int r1 = r0 + 96;
            ah[mt][0] = As[buf][r0];
            ah[mt][1] = As[buf][r1];
            ah[mt][2] = As[buf][r0 + 4];
            ah[mt][3] = As[buf][r1 + 4];
        }
#pragma unroll
        for (int nt = 0; nt < 8; nt++) {
            int ni = (wx * 64 + nt * 8 + g) * 12 + tg;
            uint32_t bh0 = Bs[buf][ni];
            uint32_t bh1 = Bs[buf][ni + 4];
#pragma unroll
            for (int mt = 0; mt < 2; mt++)
                MMA_F16(acc[mt][nt], ah[mt], bh0, bh1);
        }
        __syncthreads();

        if (t + 2 < T) {
            int k0 = (t + 2) << 4;
            if (arow_ok) cp_async16(a_dst[buf], a_src + k0);
            cp_async16(b_dst[buf], b_src + k0);
            CP_COMMIT();
        }
    }

    // ---- epilogue 1: write C as fp16 ----
#pragma unroll
    for (int mt = 0; mt < 2; mt++) {
        int gr0 = bm + wy * 32 + mt * 16 + g;
        int gr1 = gr0 + 8;
#pragma unroll
        for (int nt = 0; nt < 8; nt++) {
            int col = bn + wx * 64 + nt * 8 + 2 * tg;
            if (gr0 < M)
                C16[((size_t)gr0 * N + col) >> 1] =
                    __floats2half2_rn(acc[mt][nt][0], acc[mt][nt][1]);
            if (gr1 < M)
                C16[((size_t)gr1 * N + col) >> 1] =
                    __floats2half2_rn(acc[mt][nt][2], acc[mt][nt][3]);
        }
    }

    // ---- epilogue 2: fused attention scores ----
    const int NSLOT = (LOGC == 6) ? 1 : 2;
    float psrc[2][2][2] = {};
    float pdst[2][2][2] = {};
#pragma unroll
    for (int nt = 0; nt < 8; nt++) {
        int gc = bn + wx * 64 + nt * 8 + 2 * tg;
        float2 as = *(const float2*)&asrc[gc];
        float2 ad = *(const float2*)&adst[gc];
        int hs = (LOGC == 6) ? 0 : (nt >> 2);
#pragma unroll
        for (int mt = 0; mt < 2; mt++) {
            psrc[mt][0][hs] += acc[mt][nt][0] * as.x + acc[mt][nt][1] * as.y;
            psrc[mt][1][hs] += acc[mt][nt][2] * as.x + acc[mt][nt][3] * as.y;
            pdst[mt][0][hs] += acc[mt][nt][0] * ad.x + acc[mt][nt][1] * ad.y;
            pdst[mt][1][hs] += acc[mt][nt][2] * ad.x + acc[mt][nt][3] * ad.y;
        }
    }
#pragma unroll
    for (int mt = 0; mt < 2; mt++)
#pragma unroll
        for (int rh = 0; rh < 2; rh++)
#pragma unroll
            for (int hs = 0; hs < NSLOT; hs++) {
                float s1 = psrc[mt][rh][hs], s2 = pdst[mt][rh][hs];
                s1 += __shfl_xor_sync(0xffffffffu, s1, 1);
                s1 += __shfl_xor_sync(0xffffffffu, s1, 2);
                s2 += __shfl_xor_sync(0xffffffffu, s2, 1);
                s2 += __shfl_xor_sync(0xffffffffu, s2, 2);
                psrc[mt][rh][hs] = s1;
                pdst[mt][rh][hs] = s2;
            }
    if (tg == 0) {
#pragma unroll
        for (int mt = 0; mt < 2; mt++)
#pragma unroll
            for (int rh = 0; rh < 2; rh++) {
                int gr = bm + wy * 32 + mt * 16 + g + rh * 8;
                if (gr < M) {
#pragma unroll
                    for (int hs = 0; hs < NSLOT; hs++) {
                        int hd = (LOGC == 6) ? ((bn >> 6) + wx) : (wx * 2 + hs);
                        esrc[gr * 4 + hd] = psrc[mt][rh][hs];
                        edst[gr * 4 + hd] = pdst[mt][rh][hs];
                    }
                }
            }
    }
}

// ---------------- fused aggregation: two-pass, warp per dst node -------------
// OUT16: write fp16 output (next-layer GEMM input); else fp32 (final output).
template<int HPL, int DOELU, int OUT16>
__global__ __launch_bounds__(256) void gat_agg_kernel(
        const __half2* __restrict__ h16,
        const float* __restrict__ esrc, const float* __restrict__ edst,
        const int* __restrict__ off, const int* __restrict__ csr_src,
        const float* __restrict__ bias,
        const float* __restrict__ gam, const float* __restrict__ bet,
        float* __restrict__ outp, __half* __restrict__ outp16, int Nn) {
    const int HC  = HPL * 32;
    const int HC2 = HPL * 16;
    __shared__ float sp[8][32][4];
    __shared__ int   si[8][32];

    int wslot = threadIdx.x >> 5;
    int n = (blockIdx.x * blockDim.x + threadIdx.x) >> 5;
    int lane = threadIdx.x & 31;
    if (n >= Nn) return;
    int hd = lane >> 3;

    int beg = off[n], end = off[n + 1];
    float4 ed = ((const float4*)edst)[n];

    // pass 1: segment max per head
    float m0 = -INFINITY, m1 = -INFINITY, m2 = -INFINITY, m3 = -INFINITY;
    for (int i = beg + lane; i < end; i += 32) {
        int s = csr_src[i];
        float4 es = ((const float4*)esrc)[s];
        float e0 = es.x + ed.x; e0 = e0 > 0.f ? e0 : SLOPE * e0; m0 = fmaxf(m0, e0);
        float e1 = es.y + ed.y; e1 = e1 > 0.f ? e1 : SLOPE * e1; m1 = fmaxf(m1, e1);
        float e2 = es.z + ed.z; e2 = e2 > 0.f ? e2 : SLOPE * e2; m2 = fmaxf(m2, e2);
        float e3 = es.w + ed.w; e3 = e3 > 0.f ? e3 : SLOPE * e3; m3 = fmaxf(m3, e3);
    }
#pragma unroll
    for (int d = 16; d > 0; d >>= 1) {
        m0 = fmaxf(m0, __shfl_xor_sync(0xffffffffu, m0, d));
        m1 = fmaxf(m1, __shfl_xor_sync(0xffffffffu, m1, d));
        m2 = fmaxf(m2, __shfl_xor_sync(0xffffffffu, m2, d));
        m3 = fmaxf(m3, __shfl_xor_sync(0xffffffffu, m3, d));
    }

    // pass 2
    float acc[HPL];
#pragma unroll
    for (int j = 0; j < HPL; j++) acc[j] = 0.f;
    float den = 0.f;

    for (int i = beg; i < end; i += 32) {
        int cnt = min(32, end - i);
        int s_l = 0;
        float p0 = 0.f, p1 = 0.f, p2 = 0.f, p3 = 0.f;
        if (lane < cnt) {
            s_l = csr_src[i + lane];
            float4 es = ((const float4*)esrc)[s_l];
            float e0 = es.x + ed.x; e0 = e0 > 0.f ? e0 : SLOPE * e0;
            float e1 = es.y + ed.y; e1 = e1 > 0.f ? e1 : SLOPE * e1;
            float e2 = es.z + ed.z; e2 = e2 > 0.f ? e2 : SLOPE * e2;
            float e3 = es.w + ed.w; e3 = e3 > 0.f ? e3 : SLOPE * e3;
            p0 = __expf(e0 - m0); p1 = __expf(e1 - m1);
            p2 = __expf(e2 - m2); p3 = __expf(e3 - m3);
        }
        si[wslot][lane] = s_l;
        *(float4*)&sp[wslot][lane][0] = make_float4(p0, p1, p2, p3);
        __syncwarp();

        int k = 0;
        for (; k + 8 <= cnt; k += 8) {
            uint4 v8[8];
            uint2 v4[8];
#pragma unroll
            for (int u = 0; u < 8; u++) {
                int ss = si[wslot][k + u];
                const uint32_t* rp = (const uint32_t*)(h16 + (size_t)ss * HC2);
                if (HPL == 8) v8[u] = ((const uint4*)rp)[lane];
                else          v4[u] = ((const uint2*)rp)[lane];
            }
#pragma unroll
            for (int u = 0; u < 8; u++) {
                float q = sp[wslot][k + u][hd];
                den += q;
                uint32_t w[4];
                if (HPL == 8) { w[0] = v8[u].x; w[1] = v8[u].y; w[2] = v8[u].z; w[3] = v8[u].w; }
                else          { w[0] = v4[u].x; w[1] = v4[u].y; w[2] = 0; w[3] = 0; }
#pragma unroll
                for (int j = 0; j < HPL / 2; j++) {
                    float2 f = __half22float2(*(const __half2*)&w[j]);
                    acc[2 * j]     += q * f.x;
                    acc[2 * j + 1] += q * f.y;
                }
            }
        }
        for (; k < cnt; k++) {
            int   ss = si[wslot][k];
            float q  = sp[wslot][k][hd];
            den += q;
            const uint32_t* rp = (const uint32_t*)(h16 + (size_t)ss * HC2);
            uint32_t w[4];
            if (HPL == 8) {
                uint4 v = ((const uint4*)rp)[lane];
                w[0] = v.x; w[1] = v.y; w[2] = v.z; w[3] = v.w;
            } else {
                uint2 v = ((const uint2*)rp)[lane];
                w[0] = v.x; w[1] = v.y; w[2] = 0; w[3] = 0;
            }
#pragma unroll
            for (int j = 0; j < HPL / 2; j++) {
                float2 f = __half22float2(*(const __half2*)&w[j]);
                acc[2 * j]     += q * f.x;
                acc[2 * j + 1] += q * f.y;
            }
        }
        __syncwarp();
    }

    // epilogue: /den, +bias, (ELU), LayerNorm
    int fb = lane * HPL;
    float vals[HPL];
    float sum = 0.f;
#pragma unroll
    for (int j = 0; j < HPL; j += 4) {
        float4 b = *(const float4*)&bias[fb + j];
        float v0 = acc[j]     / den + b.x;
        float v1 = acc[j + 1] / den + b.y;
        float v2 = acc[j + 2] / den + b.z;
        float v3 = acc[j + 3] / den + b.w;
        if (DOELU) {
            v0 = v0 > 0.f ? v0 : expm1f(v0);
            v1 = v1 > 0.f ? v1 : expm1f(v1);
            v2 = v2 > 0.f ? v2 : expm1f(v2);
            v3 = v3 > 0.f ? v3 : expm1f(v3);
        }
        vals[j] = v0; vals[j + 1] = v1; vals[j + 2] = v2; vals[j + 3] = v3;
        sum += v0 + v1 + v2 + v3;
    }
#pragma unroll
    for (int d = 16; d > 0; d >>= 1) sum += __shfl_xor_sync(0xffffffffu, sum, d);
    float mu = sum / (float)HC;
    float vs = 0.f;
#pragma unroll
    for (int j = 0; j < HPL; j++) {
        float dv = vals[j] - mu;
        vs += dv * dv;
    }
#pragma unroll
    for (int d = 16; d > 0; d >>= 1) vs += __shfl_xor_sync(0xffffffffu, vs, d);
    float rstd = rsqrtf(vs / (float)HC + LN_EPS);

    float ov[HPL];
#pragma unroll
    for (int j = 0; j < HPL; j += 4) {
        float4 gm = *(const float4*)&gam[fb + j];
        float4 bt = *(const float4*)&bet[fb + j];
        ov[j]     = gm.x * (vals[j]     - mu) * rstd + bt.x;
        ov[j + 1] = gm.y * (vals[j + 1] - mu) * rstd + bt.y;
        ov[j + 2] = gm.z * (vals[j + 2] - mu) * rstd + bt.z;
        ov[j + 3] = gm.w * (vals[j + 3] - mu) * rstd + bt.w;
    }
    if (OUT16) {
        // fp16 store: HPL halves per lane, contiguous, 16B aligned for HPL=8
        union { __half2 h2[4]; uint4 u4; uint2 u2; } pk;
#pragma unroll
        for (int j = 0; j < HPL / 2; j++)
            pk.h2[j] = __floats2half2_rn(ov[2 * j], ov[2 * j + 1]);
        if (HPL == 8)
            *(uint4*)(outp16 + (size_t)n * HC + fb) = pk.u4;
        else
            *(uint2*)(outp16 + (size_t)n * HC + fb) = pk.u2;
    } else {
#pragma unroll
        for (int j = 0; j < HPL; j += 4)
            *(float4*)&outp[(size_t)n * HC + fb + j] =
                make_float4(ov[j], ov[j + 1], ov[j + 2], ov[j + 3]);
    }
}

// ---------------- mean pool: block per graph, binary search (batch sorted) ---
__global__ void pool_kernel(const float* __restrict__ node_out, const int* __restrict__ batch,
                            float* __restrict__ graph_out, int Nn) {
    int g = blockIdx.x;
    int f = threadIdx.x;  // 128
    int lo = 0, hi = Nn;
    while (lo < hi) { int mid = (lo + hi) >> 1; if (batch[mid] < g) lo = mid + 1; else hi = mid; }
    int start = lo;
    lo = start; hi = Nn;
    while (lo < hi) { int mid = (lo + hi) >> 1; if (batch[mid] < g + 1) lo = mid + 1; else hi = mid; }
    int end = lo;
    float s = 0.f;
    for (int n = start; n < end; n++) s += node_out[(size_t)n * 128 + f];
    graph_out[g * 128 + f] = s / fmaxf((float)(end - start), 1.f);
}

// ---------------- launch -----------------------------------------------------
extern "C" void kernel_launch(void* const* d_in, const int* in_sizes, int n_in,
                              void* d_out, int out_size) {
    const float* x     = (const float*)d_in[0];
    const int*   ei    = (const int*)d_in[1];
    const int*   batch = (const int*)d_in[2];
    const float* W[3]    = {(const float*)d_in[3],  (const float*)d_in[9],  (const float*)d_in[15]};
    const float* asrc[3] = {(const float*)d_in[4],  (const float*)d_in[10], (const float*)d_in[16]};
    const float* adst[3] = {(const float*)d_in[5],  (const float*)d_in[11], (const float*)d_in[17]};
    const float* bia[3]  = {(const float*)d_in[6],  (const float*)d_in[12], (const float*)d_in[18]};
    const float* gam[3]  = {(const float*)d_in[7],  (const float*)d_in[13], (const float*)d_in[19]};
    const float* bet[3]  = {(const float*)d_in[8],  (const float*)d_in[14], (const float*)d_in[20]};

    int N = in_sizes[0] / 768;
    int E = in_sizes[1] / 2;
    int Etot = E + N;
    const int* srcA = ei;
    const int* dstA = ei + E;

    float* node_out  = (float*)d_out;
    float* graph_out = node_out + (size_t)N * 128;

    __half2* p_h16;
    __half *p_in16, *p_x16, *p_w16t;
    float *p_esrc, *p_edst;
    int *p_deg, *p_off, *p_cur, *p_csr, *p_bsum, *p_boff;
    cudaGetSymbolAddress((void**)&p_h16, g_h16_raw);
    cudaGetSymbolAddress((void**)&p_in16, g_in16_raw);
    cudaGetSymbolAddress((void**)&p_x16, g_x16_raw);
    cudaGetSymbolAddress((void**)&p_w16t, g_w16t);
    cudaGetSymbolAddress((void**)&p_esrc, g_esrc);
    cudaGetSymbolAddress((void**)&p_edst, g_edst);
    cudaGetSymbolAddress((void**)&p_deg, g_deg);
    cudaGetSymbolAddress((void**)&p_off, g_off);
    cudaGetSymbolAddress((void**)&p_cur, g_cur);
    cudaGetSymbolAddress((void**)&p_csr, g_csr);
    cudaGetSymbolAddress((void**)&p_bsum, g_bsum);
    cudaGetSymbolAddress((void**)&p_boff, g_boff);

    __half* Wt[3] = {p_w16t, p_w16t + 256 * 768, p_w16t + 256 * 768 + 256 * 256};

    int dins[3] = {768, 256, 256};
    int HCs[3]  = {256, 256, 128};
    const __half* inputs[3] = {p_x16, p_in16, p_in16};

    // 1: convert x -> fp16
    int n4 = N * 768 / 4;
    conv_x16_kernel<<<(n4 + 255) / 256, 256>>>(x, p_x16, n4);
    // 2: convert + transpose weights -> fp16 [HC, K]
    {
        dim3 wgrid(8, 24, 3);
        conv_wt_kernel<<<wgrid, dim3(32, 8)>>>(W[0], W[1], W[2], Wt[0], Wt[1], Wt[2]);
    }
    // 3: CSR degree init
    init_deg_kernel<<<(N + 255) / 256, 256>>>(p_deg, p_cur, N);
    // 4: layer-1 HGEMM (profiled position)
    {
        dim3 ggrid(2, (N + 127) / 128);
        hgemm_scores_kernel<6><<<ggrid, 256>>>(inputs[0], Wt[0], p_h16,
                                               asrc[0], adst[0], p_esrc, p_edst,
                                               N, dins[0], HCs[0]);
    }
    // CSR build
    int nb = (N + 255) / 256;
    deg_hist_kernel<<<(E + 255) / 256, 256>>>(dstA, E, p_deg);
    block_sum_kernel<<<nb, 256>>>(p_deg, p_bsum, N);
    scan_bsums_kernel<<<1, 256>>>(p_bsum, p_boff, nb, p_off, N);
    block_scan_kernel<<<nb, 256>>>(p_deg, p_boff, p_off, N);
    csr_scatter_kernel<<<(Etot + 255) / 256, 256>>>(srcA, dstA, E, Etot, p_off, p_cur, p_csr);

    int nwb = (N + 7) / 8;
    for (int L = 0; L < 3; L++) {
        int K = dins[L], HC = HCs[L];

        if (L > 0) {
            dim3 ggrid(HC / 128, (N + 127) / 128);
            if (HC == 256)
                hgemm_scores_kernel<6><<<ggrid, 256>>>(inputs[L], Wt[L], p_h16,
                                                       asrc[L], adst[L], p_esrc, p_edst,
                                                       N, K, HC);
            else
                hgemm_scores_kernel<5><<<ggrid, 256>>>(inputs[L], Wt[L], p_h16,
                                                       asrc[L], adst[L], p_esrc, p_edst,
                                                       N, K, HC);
        }

        if (HC == 256) {
            if (L < 2)
                gat_agg_kernel<8, 1, 1><<<nwb, 256>>>(p_h16, p_esrc, p_edst, p_off, p_csr,
                                                      bia[L], gam[L], bet[L],
                                                      nullptr, p_in16, N);
            else
                gat_agg_kernel<8, 0, 0><<<nwb, 256>>>(p_h16, p_esrc, p_edst, p_off, p_csr,
                                                      bia[L], gam[L], bet[L],
                                                      node_out, nullptr, N);
        } else {
            gat_agg_kernel<4, 0, 0><<<nwb, 256>>>(p_h16, p_esrc, p_edst, p_off, p_csr,
                                                  bia[L], gam[L], bet[L],
                                                  node_out, nullptr, N);
        }
    }

    pool_kernel<<<GMAX, 128>>>(node_out, batch, graph_out, N);
}

// round 17
// speedup vs baseline: 1.2121x; 1.0409x over previous
#include <cuda_runtime.h>
#include <cuda_fp16.h>
#include <math.h>
#include <stdint.h>

#define NMAX 50000
#define EMAX 800000
#define ETOTMAX (EMAX + NMAX)
#define GMAX 64
#define LN_EPS 1e-5f
#define SLOPE 0.2f

// ---------------- scratch (static device globals; no runtime alloc) ----------
__device__ uint4  g_h16_raw[(size_t)NMAX * 32];   // fp16 GEMM output (256 halves/node)
__device__ uint4  g_in16_raw[(size_t)NMAX * 32];  // fp16 normalized features (next-layer input)
__device__ uint4  g_x16_raw[(size_t)NMAX * 96];   // fp16 copy of x (768 halves/node)
__device__ __half g_w16t[256 * 768 + 256 * 256 + 128 * 256];  // transposed fp16 weights
__device__ float g_esrc[NMAX * 4];
__device__ float g_edst[NMAX * 4];
__device__ int   g_deg [NMAX + 1];
__device__ int   g_off [NMAX + 1];
__device__ int   g_cur [NMAX];
__device__ int   g_csr [ETOTMAX];
__device__ int   g_bsum[256];
__device__ int   g_boff[256];

// ---------------- cp.async / ldmatrix helpers --------------------------------
__device__ __forceinline__ void cp_async16(uint32_t smem_addr, const void* gptr) {
    asm volatile("cp.async.cg.shared.global [%0], [%1], 16;\n"
                 :: "r"(smem_addr), "l"(gptr));
}
#define CP_COMMIT() asm volatile("cp.async.commit_group;\n" ::: "memory")
#define CP_WAIT(N)  asm volatile("cp.async.wait_group %0;\n" :: "n"(N) : "memory")

__device__ __forceinline__ void ldsm_x4(uint32_t& r0, uint32_t& r1, uint32_t& r2, uint32_t& r3,
                                        uint32_t addr) {
    asm volatile("ldmatrix.sync.aligned.m8n8.x4.shared.b16 {%0,%1,%2,%3}, [%4];\n"
                 : "=r"(r0), "=r"(r1), "=r"(r2), "=r"(r3) : "r"(addr));
}

// ---------------- input conversion -------------------------------------------
__global__ void conv_x16_kernel(const float* __restrict__ x, __half* __restrict__ x16, int n4) {
    int i = blockIdx.x * blockDim.x + threadIdx.x;
    if (i >= n4) return;
    float4 v = ((const float4*)x)[i];
    union { __half2 h2[2]; uint2 u; } pk;
    pk.h2[0] = __floats2half2_rn(v.x, v.y);
    pk.h2[1] = __floats2half2_rn(v.z, v.w);
    ((uint2*)x16)[i] = pk.u;
}

// W [K, HC] fp32 -> Wt [HC, K] fp16
__global__ void conv_wt_kernel(const float* __restrict__ W1, const float* __restrict__ W2,
                               const float* __restrict__ W3,
                               __half* __restrict__ Wt1, __half* __restrict__ Wt2,
                               __half* __restrict__ Wt3) {
    __shared__ float tile[32][33];
    int l = blockIdx.z;
    const float* W = (l == 0) ? W1 : (l == 1) ? W2 : W3;
    __half* Wt = (l == 0) ? Wt1 : (l == 1) ? Wt2 : Wt3;
    int K  = (l == 0) ? 768 : 256;
    int HC = (l == 2) ? 128 : 256;
    int kb = blockIdx.y * 32, nb = blockIdx.x * 32;
    if (kb >= K || nb >= HC) return;
    int tx = threadIdx.x, ty = threadIdx.y;   // 32 x 8
#pragma unroll
    for (int j = 0; j < 32; j += 8)
        tile[ty + j][tx] = W[(size_t)(kb + ty + j) * HC + nb + tx];
    __syncthreads();
#pragma unroll
    for (int j = 0; j < 32; j += 8)
        Wt[(size_t)(nb + ty + j) * K + kb + tx] = __float2half_rn(tile[tx][ty + j]);
}

// ---------------- CSR build --------------------------------------------------
__global__ void init_deg_kernel(int* __restrict__ deg, int* __restrict__ cur, int Nn) {
    int i = blockIdx.x * blockDim.x + threadIdx.x;
    if (i < Nn) { deg[i] = 1; cur[i] = 0; }
}

__global__ void deg_hist_kernel(const int* __restrict__ dst, int E_, int* __restrict__ deg) {
    int i = blockIdx.x * blockDim.x + threadIdx.x;
    if (i < E_) atomicAdd(&deg[dst[i]], 1);
}

__global__ void block_sum_kernel(const int* __restrict__ deg, int* __restrict__ bsum, int n) {
    __shared__ int red[256];
    int idx = blockIdx.x * 256 + threadIdx.x;
    red[threadIdx.x] = (idx < n) ? deg[idx] : 0;
    __syncthreads();
    for (int s = 128; s > 0; s >>= 1) {
        if (threadIdx.x < s) red[threadIdx.x] += red[threadIdx.x + s];
        __syncthreads();
    }
    if (threadIdx.x == 0) bsum[blockIdx.x] = red[0];
}

__global__ void scan_bsums_kernel(const int* __restrict__ bsum, int* __restrict__ boff,
                                  int nb, int* __restrict__ off, int n) {
    __shared__ int ws[8];
    int tid = threadIdx.x, lane = tid & 31, wid = tid >> 5;
    int v = (tid < nb) ? bsum[tid] : 0;
    int incl = v;
#pragma unroll
    for (int d = 1; d < 32; d <<= 1) {
        int t = __shfl_up_sync(0xffffffffu, incl, d);
        if (lane >= d) incl += t;
    }
    if (lane == 31) ws[wid] = incl;
    __syncthreads();
    if (tid == 0) {
        int c = 0;
#pragma unroll
        for (int i = 0; i < 8; i++) { int t = ws[i]; ws[i] = c; c += t; }
        off[n] = c;
    }
    __syncthreads();
    if (tid < nb) boff[tid] = ws[wid] + incl - v;
}

__global__ void block_scan_kernel(const int* __restrict__ deg, const int* __restrict__ boff,
                                  int* __restrict__ off, int n) {
    __shared__ int ws[8];
    int idx = blockIdx.x * 256 + threadIdx.x;
    int lane = threadIdx.x & 31, wid = threadIdx.x >> 5;
    int v = (idx < n) ? deg[idx] : 0;
    int incl = v;
#pragma unroll
    for (int d = 1; d < 32; d <<= 1) {
        int t = __shfl_up_sync(0xffffffffu, incl, d);
        if (lane >= d) incl += t;
    }
    if (lane == 31) ws[wid] = incl;
    __syncthreads();
    if (threadIdx.x == 0) {
        int c = 0;
#pragma unroll
        for (int i = 0; i < 8; i++) { int t = ws[i]; ws[i] = c; c += t; }
    }
    __syncthreads();
    if (idx < n) off[idx] = boff[blockIdx.x] + ws[wid] + incl - v;
}

__global__ void csr_scatter_kernel(const int* __restrict__ src, const int* __restrict__ dst,
                                   int E_, int Etot,
                                   const int* __restrict__ off, int* __restrict__ cur,
                                   int* __restrict__ csr_src) {
    int i = blockIdx.x * blockDim.x + threadIdx.x;
    if (i >= Etot) return;
    int s, d;
    if (i < E_) { s = src[i]; d = dst[i]; } else { s = d = i - E_; }
    int pos = off[d] + atomicAdd(&cur[d], 1);
    csr_src[pos] = s;
}

// ---------------- fp16 HGEMM: cp.async + ldmatrix, fused scores --------------
// C16[M,N] = A16[M,K] @ B16t[N,K]^T. BN=128, BK=16, 256 threads, 8 warps.
// smem rows: 8 words data x2 chunks + 4 pad -> stride 12 words (48B); the 8
// ldmatrix row-reads tile all 32 banks exactly once (conflict-free).

#define MMA_F16(d, a0, a1, a2, a3, b0, b1)                                   \
    asm volatile("mma.sync.aligned.m16n8k16.row.col.f32.f16.f16.f32 "        \
                 "{%0,%1,%2,%3}, {%4,%5,%6,%7}, {%8,%9}, {%0,%1,%2,%3};\n"   \
                 : "+f"(d[0]), "+f"(d[1]), "+f"(d[2]), "+f"(d[3])            \
                 : "r"(a0), "r"(a1), "r"(a2), "r"(a3), "r"(b0), "r"(b1))

template<int LOGC>
__global__ __launch_bounds__(256) void hgemm_scores_kernel(
        const __half* __restrict__ A16, const __half* __restrict__ B16t,
        __half2* __restrict__ C16,
        const float* __restrict__ asrc, const float* __restrict__ adst,
        float* __restrict__ esrc, float* __restrict__ edst,
        int M, int K, int N) {
    __shared__ uint32_t As[2][128 * 12];
    __shared__ uint32_t Bs[2][128 * 12];

    const int tid = threadIdx.x;
    const int warp = tid >> 5, lane = tid & 31;
    const int g = lane >> 2, tg = lane & 3;
    const int wy = warp & 3, wx = warp >> 2;
    const int bm = blockIdx.y * 128, bn = blockIdx.x * 128;

    // loader: thread owns one 16B A chunk + one 16B B chunk per k-tile
    const int lrow  = tid >> 1;
    const int lpart = tid & 1;
    const bool arow_ok = (bm + lrow) < M;
    uint32_t a_dst[2], b_dst[2];
    a_dst[0] = (uint32_t)__cvta_generic_to_shared(&As[0][lrow * 12 + lpart * 4]);
    a_dst[1] = (uint32_t)__cvta_generic_to_shared(&As[1][lrow * 12 + lpart * 4]);
    b_dst[0] = (uint32_t)__cvta_generic_to_shared(&Bs[0][lrow * 12 + lpart * 4]);
    b_dst[1] = (uint32_t)__cvta_generic_to_shared(&Bs[1][lrow * 12 + lpart * 4]);
    const __half* a_src = A16 + (size_t)(bm + lrow) * K + lpart * 8;
    const __half* b_src = B16t + (size_t)(bn + lrow) * K + lpart * 8;

    if (!arow_ok) {
        uint4 z = make_uint4(0, 0, 0, 0);
        *(uint4*)&As[0][lrow * 12 + lpart * 4] = z;
        *(uint4*)&As[1][lrow * 12 + lpart * 4] = z;
    }

    // ldmatrix addresses: lane -> row (lane&15), k-half (lane>>4)
    const uint32_t bufstride = 128 * 12 * 4;
    uint32_t a_lds = (uint32_t)__cvta_generic_to_shared(
        &As[0][(wy * 32 + (lane & 15)) * 12 + ((lane >> 4) << 2)]);
    uint32_t b_lds = (uint32_t)__cvta_generic_to_shared(
        &Bs[0][(wx * 64 + (lane & 15)) * 12 + ((lane >> 4) << 2)]);

    float acc[2][8][4];
#pragma unroll
    for (int mt = 0; mt < 2; mt++)
#pragma unroll
        for (int nt = 0; nt < 8; nt++)
#pragma unroll
            for (int c = 0; c < 4; c++) acc[mt][nt][c] = 0.f;

    const int T = K >> 4;

    if (arow_ok) cp_async16(a_dst[0], a_src);
    cp_async16(b_dst[0], b_src);
    CP_COMMIT();
    if (T > 1) {
        if (arow_ok) cp_async16(a_dst[1], a_src + 16);
        cp_async16(b_dst[1], b_src + 16);
        CP_COMMIT();
    }

    for (int t = 0; t < T; t++) {
        if (t + 1 < T) { CP_WAIT(1); } else { CP_WAIT(0); }
        __syncthreads();
        const int buf = t & 1;
        const uint32_t boff = buf * bufstride;

        // A fragments: 2x ldmatrix.x4 (a0..a3 per mt)
        uint32_t ah[2][4];
        ldsm_x4(ah[0][0], ah[0][1], ah[0][2], ah[0][3], a_lds + boff);
        ldsm_x4(ah[1][0], ah[1][1], ah[1][2], ah[1][3], a_lds + boff + 16 * 48);

        // B fragments: 4x ldmatrix.x4, each covering nt pair (2*ntp, 2*ntp+1)
        // r0 = even b0, r1 = odd b0, r2 = even b1, r3 = odd b1
        uint32_t bq[4][4];
#pragma unroll
        for (int ntp = 0; ntp < 4; ntp++)
            ldsm_x4(bq[ntp][0], bq[ntp][1], bq[ntp][2], bq[ntp][3],
                    b_lds + boff + ntp * 16 * 48);

#pragma unroll
        for (int ntp = 0; ntp < 4; ntp++) {
#pragma unroll
            for (int mt = 0; mt < 2; mt++) {
                MMA_F16(acc[mt][2 * ntp],     ah[mt][0], ah[mt][1], ah[mt][2], ah[mt][3],
                        bq[ntp][0], bq[ntp][2]);
                MMA_F16(acc[mt][2 * ntp + 1], ah[mt][0], ah[mt][1], ah[mt][2], ah[mt][3],
                        bq[ntp][1], bq[ntp][3]);
            }
        }
        __syncthreads();

        if (t + 2 < T) {
            int k0 = (t + 2) << 4;
            if (arow_ok) cp_async16(a_dst[buf], a_src + k0);
            cp_async16(b_dst[buf], b_src + k0);
            CP_COMMIT();
        }
    }

    // ---- epilogue 1: write C as fp16 ----
#pragma unroll
    for (int mt = 0; mt < 2; mt++) {
        int gr0 = bm + wy * 32 + mt * 16 + g;
        int gr1 = gr0 + 8;
#pragma unroll
        for (int nt = 0; nt < 8; nt++) {
            int col = bn + wx * 64 + nt * 8 + 2 * tg;
            if (gr0 < M)
                C16[((size_t)gr0 * N + col) >> 1] =
                    __floats2half2_rn(acc[mt][nt][0], acc[mt][nt][1]);
            if (gr1 < M)
                C16[((size_t)gr1 * N + col) >> 1] =
                    __floats2half2_rn(acc[mt][nt][2], acc[mt][nt][3]);
        }
    }

    // ---- epilogue 2: fused attention scores ----
    const int NSLOT = (LOGC == 6) ? 1 : 2;
    float psrc[2][2][2] = {};
    float pdst[2][2][2] = {};
#pragma unroll
    for (int nt = 0; nt < 8; nt++) {
        int gc = bn + wx * 64 + nt * 8 + 2 * tg;
        float2 as = *(const float2*)&asrc[gc];
        float2 ad = *(const float2*)&adst[gc];
        int hs = (LOGC == 6) ? 0 : (nt >> 2);
#pragma unroll
        for (int mt = 0; mt < 2; mt++) {
            psrc[mt][0][hs] += acc[mt][nt][0] * as.x + acc[mt][nt][1] * as.y;
            psrc[mt][1][hs] += acc[mt][nt][2] * as.x + acc[mt][nt][3] * as.y;
            pdst[mt][0][hs] += acc[mt][nt][0] * ad.x + acc[mt][nt][1] * ad.y;
            pdst[mt][1][hs] += acc[mt][nt][2] * ad.x + acc[mt][nt][3] * ad.y;
        }
    }
#pragma unroll
    for (int mt = 0; mt < 2; mt++)
#pragma unroll
        for (int rh = 0; rh < 2; rh++)
#pragma unroll
            for (int hs = 0; hs < NSLOT; hs++) {
                float s1 = psrc[mt][rh][hs], s2 = pdst[mt][rh][hs];
                s1 += __shfl_xor_sync(0xffffffffu, s1, 1);
                s1 += __shfl_xor_sync(0xffffffffu, s1, 2);
                s2 += __shfl_xor_sync(0xffffffffu, s2, 1);
                s2 += __shfl_xor_sync(0xffffffffu, s2, 2);
                psrc[mt][rh][hs] = s1;
                pdst[mt][rh][hs] = s2;
            }
    if (tg == 0) {
#pragma unroll
        for (int mt = 0; mt < 2; mt++)
#pragma unroll
            for (int rh = 0; rh < 2; rh++) {
                int gr = bm + wy * 32 + mt * 16 + g + rh * 8;
                if (gr < M) {
#pragma unroll
                    for (int hs = 0; hs < NSLOT; hs++) {
                        int hd = (LOGC == 6) ? ((bn >> 6) + wx) : (wx * 2 + hs);
                        esrc[gr * 4 + hd] = psrc[mt][rh][hs];
                        edst[gr * 4 + hd] = pdst[mt][rh][hs];
                    }
                }
            }
    }
}

// ---------------- fused aggregation: two-pass, warp per dst node -------------
template<int HPL, int DOELU, int OUT16>
__global__ __launch_bounds__(256) void gat_agg_kernel(
        const __half2* __restrict__ h16,
        const float* __restrict__ esrc, const float* __restrict__ edst,
        const int* __restrict__ off, const int* __restrict__ csr_src,
        const float* __restrict__ bias,
        const float* __restrict__ gam, const float* __restrict__ bet,
        float* __restrict__ outp, __half* __restrict__ outp16, int Nn) {
    const int HC  = HPL * 32;
    const int HC2 = HPL * 16;
    __shared__ float sp[8][32][4];
    __shared__ int   si[8][32];

    int wslot = threadIdx.x >> 5;
    int n = (blockIdx.x * blockDim.x + threadIdx.x) >> 5;
    int lane = threadIdx.x & 31;
    if (n >= Nn) return;
    int hd = lane >> 3;

    int beg = off[n], end = off[n + 1];
    float4 ed = ((const float4*)edst)[n];

    // pass 1: segment max per head
    float m0 = -INFINITY, m1 = -INFINITY, m2 = -INFINITY, m3 = -INFINITY;
    for (int i = beg + lane; i < end; i += 32) {
        int s = csr_src[i];
        float4 es = ((const float4*)esrc)[s];
        float e0 = es.x + ed.x; e0 = e0 > 0.f ? e0 : SLOPE * e0; m0 = fmaxf(m0, e0);
        float e1 = es.y + ed.y; e1 = e1 > 0.f ? e1 : SLOPE * e1; m1 = fmaxf(m1, e1);
        float e2 = es.z + ed.z; e2 = e2 > 0.f ? e2 : SLOPE * e2; m2 = fmaxf(m2, e2);
        float e3 = es.w + ed.w; e3 = e3 > 0.f ? e3 : SLOPE * e3; m3 = fmaxf(m3, e3);
    }
#pragma unroll
    for (int d = 16; d > 0; d >>= 1) {
        m0 = fmaxf(m0, __shfl_xor_sync(0xffffffffu, m0, d));
        m1 = fmaxf(m1, __shfl_xor_sync(0xffffffffu, m1, d));
        m2 = fmaxf(m2, __shfl_xor_sync(0xffffffffu, m2, d));
        m3 = fmaxf(m3, __shfl_xor_sync(0xffffffffu, m3, d));
    }

    // pass 2
    float acc[HPL];
#pragma unroll
    for (int j = 0; j < HPL; j++) acc[j] = 0.f;
    float den = 0.f;

    for (int i = beg; i < end; i += 32) {
        int cnt = min(32, end - i);
        int s_l = 0;
        float p0 = 0.f, p1 = 0.f, p2 = 0.f, p3 = 0.f;
        if (lane < cnt) {
            s_l = csr_src[i + lane];
            float4 es = ((const float4*)esrc)[s_l];
            float e0 = es.x + ed.x; e0 = e0 > 0.f ? e0 : SLOPE * e0;
            float e1 = es.y + ed.y; e1 = e1 > 0.f ? e1 : SLOPE * e1;
            float e2 = es.z + ed.z; e2 = e2 > 0.f ? e2 : SLOPE * e2;
            float e3 = es.w + ed.w; e3 = e3 > 0.f ? e3 : SLOPE * e3;
            p0 = __expf(e0 - m0); p1 = __expf(e1 - m1);
            p2 = __expf(e2 - m2); p3 = __expf(e3 - m3);
        }
        si[wslot][lane] = s_l;
        *(float4*)&sp[wslot][lane][0] = make_float4(p0, p1, p2, p3);
        __syncwarp();

        int k = 0;
        for (; k + 8 <= cnt; k += 8) {
            uint4 v8[8];
            uint2 v4[8];
#pragma unroll
            for (int u = 0; u < 8; u++) {
                int ss = si[wslot][k + u];
                const uint32_t* rp = (const uint32_t*)(h16 + (size_t)ss * HC2);
                if (HPL == 8) v8[u] = ((const uint4*)rp)[lane];
                else          v4[u] = ((const uint2*)rp)[lane];
            }
#pragma unroll
            for (int u = 0; u < 8; u++) {
                float q = sp[wslot][k + u][hd];
                den += q;
                uint32_t w[4];
                if (HPL == 8) { w[0] = v8[u].x; w[1] = v8[u].y; w[2] = v8[u].z; w[3] = v8[u].w; }
                else          { w[0] = v4[u].x; w[1] = v4[u].y; w[2] = 0; w[3] = 0; }
#pragma unroll
                for (int j = 0; j < HPL / 2; j++) {
                    float2 f = __half22float2(*(const __half2*)&w[j]);
                    acc[2 * j]     += q * f.x;
                    acc[2 * j + 1] += q * f.y;
                }
            }
        }
        for (; k < cnt; k++) {
            int   ss = si[wslot][k];
            float q  = sp[wslot][k][hd];
            den += q;
            const uint32_t* rp = (const uint32_t*)(h16 + (size_t)ss * HC2);
            uint32_t w[4];
            if (HPL == 8) {
                uint4 v = ((const uint4*)rp)[lane];
                w[0] = v.x; w[1] = v.y; w[2] = v.z; w[3] = v.w;
            } else {
                uint2 v = ((const uint2*)rp)[lane];
                w[0] = v.x; w[1] = v.y; w[2] = 0; w[3] = 0;
            }
#pragma unroll
            for (int j = 0; j < HPL / 2; j++) {
                float2 f = __half22float2(*(const __half2*)&w[j]);
                acc[2 * j]     += q * f.x;
                acc[2 * j + 1] += q * f.y;
            }
        }
        __syncwarp();
    }

    // epilogue: /den, +bias, (ELU), LayerNorm
    int fb = lane * HPL;
    float vals[HPL];
    float sum = 0.f;
#pragma unroll
    for (int j = 0; j < HPL; j += 4) {
        float4 b = *(const float4*)&bias[fb + j];
        float v0 = acc[j]     / den + b.x;
        float v1 = acc[j + 1] / den + b.y;
        float v2 = acc[j + 2] / den + b.z;
        float v3 = acc[j + 3] / den + b.w;
        if (DOELU) {
            v0 = v0 > 0.f ? v0 : expm1f(v0);
            v1 = v1 > 0.f ? v1 : expm1f(v1);
            v2 = v2 > 0.f ? v2 : expm1f(v2);
            v3 = v3 > 0.f ? v3 : expm1f(v3);
        }
        vals[j] = v0; vals[j + 1] = v1; vals[j + 2] = v2; vals[j + 3] = v3;
        sum += v0 + v1 + v2 + v3;
    }
#pragma unroll
    for (int d = 16; d > 0; d >>= 1) sum += __shfl_xor_sync(0xffffffffu, sum, d);
    float mu = sum / (float)HC;
    float vs = 0.f;
#pragma unroll
    for (int j = 0; j < HPL; j++) {
        float dv = vals[j] - mu;
        vs += dv * dv;
    }
#pragma unroll
    for (int d = 16; d > 0; d >>= 1) vs += __shfl_xor_sync(0xffffffffu, vs, d);
    float rstd = rsqrtf(vs / (float)HC + LN_EPS);

    float ov[HPL];
#pragma unroll
    for (int j = 0; j < HPL; j += 4) {
        float4 gm = *(const float4*)&gam[fb + j];
        float4 bt = *(const float4*)&bet[fb + j];
        ov[j]     = gm.x * (vals[j]     - mu) * rstd + bt.x;
        ov[j + 1] = gm.y * (vals[j + 1] - mu) * rstd + bt.y;
        ov[j + 2] = gm.z * (vals[j + 2] - mu) * rstd + bt.z;
        ov[j + 3] = gm.w * (vals[j + 3] - mu) * rstd + bt.w;
    }
    if (OUT16) {
        union { __half2 h2[4]; uint4 u4; uint2 u2; } pk;
#pragma unroll
        for (int j = 0; j < HPL / 2; j++)
            pk.h2[j] = __floats2half2_rn(ov[2 * j], ov[2 * j + 1]);
        if (HPL == 8)
            *(uint4*)(outp16 + (size_t)n * HC + fb) = pk.u4;
        else
            *(uint2*)(outp16 + (size_t)n * HC + fb) = pk.u2;
    } else {
#pragma unroll
        for (int j = 0; j < HPL; j += 4)
            *(float4*)&outp[(size_t)n * HC + fb + j] =
                make_float4(ov[j], ov[j + 1], ov[j + 2], ov[j + 3]);
    }
}

// ---------------- mean pool: block per graph, binary search (batch sorted) ---
__global__ void pool_kernel(const float* __restrict__ node_out, const int* __restrict__ batch,
                            float* __restrict__ graph_out, int Nn) {
    int g = blockIdx.x;
    int f = threadIdx.x;  // 128
    int lo = 0, hi = Nn;
    while (lo < hi) { int mid = (lo + hi) >> 1; if (batch[mid] < g) lo = mid + 1; else hi = mid; }
    int start = lo;
    lo = start; hi = Nn;
    while (lo < hi) { int mid = (lo + hi) >> 1; if (batch[mid] < g + 1) lo = mid + 1; else hi = mid; }
    int end = lo;
    float s = 0.f;
    for (int n = start; n < end; n++) s += node_out[(size_t)n * 128 + f];
    graph_out[g * 128 + f] = s / fmaxf((float)(end - start), 1.f);
}

// ---------------- launch -----------------------------------------------------
extern "C" void kernel_launch(void* const* d_in, const int* in_sizes, int n_in,
                              void* d_out, int out_size) {
    const float* x     = (const float*)d_in[0];
    const int*   ei    = (const int*)d_in[1];
    const int*   batch = (const int*)d_in[2];
    const float* W[3]    = {(const float*)d_in[3],  (const float*)d_in[9],  (const float*)d_in[15]};
    const float* asrc[3] = {(const float*)d_in[4],  (const float*)d_in[10], (const float*)d_in[16]};
    const float* adst[3] = {(const float*)d_in[5],  (const float*)d_in[11], (const float*)d_in[17]};
    const float* bia[3]  = {(const float*)d_in[6],  (const float*)d_in[12], (const float*)d_in[18]};
    const float* gam[3]  = {(const float*)d_in[7],  (const float*)d_in[13], (const float*)d_in[19]};
    const float* bet[3]  = {(const float*)d_in[8],  (const float*)d_in[14], (const float*)d_in[20]};

    int N = in_sizes[0] / 768;
    int E = in_sizes[1] / 2;
    int Etot = E + N;
    const int* srcA = ei;
    const int* dstA = ei + E;

    float* node_out  = (float*)d_out;
    float* graph_out = node_out + (size_t)N * 128;

    __half2* p_h16;
    __half *p_in16, *p_x16, *p_w16t;
    float *p_esrc, *p_edst;
    int *p_deg, *p_off, *p_cur, *p_csr, *p_bsum, *p_boff;
    cudaGetSymbolAddress((void**)&p_h16, g_h16_raw);
    cudaGetSymbolAddress((void**)&p_in16, g_in16_raw);
    cudaGetSymbolAddress((void**)&p_x16, g_x16_raw);
    cudaGetSymbolAddress((void**)&p_w16t, g_w16t);
    cudaGetSymbolAddress((void**)&p_esrc, g_esrc);
    cudaGetSymbolAddress((void**)&p_edst, g_edst);
    cudaGetSymbolAddress((void**)&p_deg, g_deg);
    cudaGetSymbolAddress((void**)&p_off, g_off);
    cudaGetSymbolAddress((void**)&p_cur, g_cur);
    cudaGetSymbolAddress((void**)&p_csr, g_csr);
    cudaGetSymbolAddress((void**)&p_bsum, g_bsum);
    cudaGetSymbolAddress((void**)&p_boff, g_boff);

    __half* Wt[3] = {p_w16t, p_w16t + 256 * 768, p_w16t + 256 * 768 + 256 * 256};

    int dins[3] = {768, 256, 256};
    int HCs[3]  = {256, 256, 128};
    const __half* inputs[3] = {p_x16, p_in16, p_in16};

    int n4 = N * 768 / 4;
    conv_x16_kernel<<<(n4 + 255) / 256, 256>>>(x, p_x16, n4);
    {
        dim3 wgrid(8, 24, 3);
        conv_wt_kernel<<<wgrid, dim3(32, 8)>>>(W[0], W[1], W[2], Wt[0], Wt[1], Wt[2]);
    }
    init_deg_kernel<<<(N + 255) / 256, 256>>>(p_deg, p_cur, N);
    // launch #4: layer-1 HGEMM (profiled position)
    {
        dim3 ggrid(2, (N + 127) / 128);
        hgemm_scores_kernel<6><<<ggrid, 256>>>(inputs[0], Wt[0], p_h16,
                                               asrc[0], adst[0], p_esrc, p_edst,
                                               N, dins[0], HCs[0]);
    }
    int nb = (N + 255) / 256;
    deg_hist_kernel<<<(E + 255) / 256, 256>>>(dstA, E, p_deg);
    block_sum_kernel<<<nb, 256>>>(p_deg, p_bsum, N);
    scan_bsums_kernel<<<1, 256>>>(p_bsum, p_boff, nb, p_off, N);
    block_scan_kernel<<<nb, 256>>>(p_deg, p_boff, p_off, N);
    csr_scatter_kernel<<<(Etot + 255) / 256, 256>>>(srcA, dstA, E, Etot, p_off, p_cur, p_csr);

    int nwb = (N + 7) / 8;
    for (int L = 0; L < 3; L++) {
        int K = dins[L], HC = HCs[L];

        if (L > 0) {
            dim3 ggrid(HC / 128, (N + 127) / 128);
            if (HC == 256)
                hgemm_scores_kernel<6><<<ggrid, 256>>>(inputs[L], Wt[L], p_h16,
                                                       asrc[L], adst[L], p_esrc, p_edst,
                                                       N, K, HC);
            else
                hgemm_scores_kernel<5><<<ggrid, 256>>>(inputs[L], Wt[L], p_h16,
                                                       asrc[L], adst[L], p_esrc, p_edst,
                                                       N, K, HC);
        }

        if (HC == 256) {
            if (L < 2)
                gat_agg_kernel<8, 1, 1><<<nwb, 256>>>(p_h16, p_esrc, p_edst, p_off, p_csr,
                                                      bia[L], gam[L], bet[L],
                                                      nullptr, p_in16, N);
            else
                gat_agg_kernel<8, 0, 0><<<nwb, 256>>>(p_h16, p_esrc, p_edst, p_off, p_csr,
                                                      bia[L], gam[L], bet[L],
                                                      node_out, nullptr, N);
        } else {
            gat_agg_kernel<4, 0, 0><<<nwb, 256>>>(p_h16, p_esrc, p_edst, p_off, p_csr,
                                                  bia[L], gam[L], bet[L],
                                                  node_out, nullptr, N);
        }
    }

    pool_kernel<<<GMAX, 128>>>(node_out, batch, graph_out, N);
}